// round 13
// baseline (speedup 1.0000x reference)
#include <cuda_runtime.h>

#define NN 20000
#define EE 160000
#define E2 320000
#define HH 128
#define TILE 32
#define NT (NN / TILE)   // 625, exact
#define TB2 512

#define MM_ACC 1
#define MM_RELU 2
#define MM_BIAS 4
#define MM_BIASDEG 8

typedef unsigned long long ull;

__device__ __forceinline__ ull pk2(float x) {
    ull r; asm("mov.b64 %0,{%1,%1};" : "=l"(r) : "f"(x)); return r;
}
__device__ __forceinline__ ull pkxy(float x, float y) {
    ull r; asm("mov.b64 %0,{%1,%2};" : "=l"(r) : "f"(x), "f"(y)); return r;
}
__device__ __forceinline__ ull fma2(ull a, ull b, ull c) {
    ull d; asm("fma.rn.f32x2 %0,%1,%2,%3;" : "=l"(d) : "l"(a), "l"(b), "l"(c)); return d;
}
__device__ __forceinline__ ull add2(ull a, ull b) {
    ull d; asm("add.rn.f32x2 %0,%1,%2;" : "=l"(d) : "l"(a), "l"(b)); return d;
}
__device__ __forceinline__ void upk(ull v, float& x, float& y) {
    asm("mov.b64 {%0,%1},%2;" : "=f"(x), "=f"(y) : "l"(v));
}

// ---------------- scratch ----------------
__device__ float g_h[NN * HH];
__device__ float g_adst[NN * HH];
__device__ float g_asrc[NN * HH];
__device__ float g_t1[NN * HH];
__device__ float g_t2[NN * HH];
__device__ float g_out[NN * HH];
__device__ float g_dis[NN];
__device__ float g_degf[NN];
__device__ int g_rowptr[NN + 1];
__device__ int g_cursor[NN];
__device__ int g_blocksum[32];
__device__ int4 g_csr[E2];   // (src, ea_row, bitcast(norm), 0)

// ---------------- fused: zero cursor + mask MLP ----------------
__global__ void k_zero_maskmlp(const float* __restrict__ x, const float* __restrict__ mask,
                               const float* __restrict__ w1, const float* __restrict__ b1,
                               const float* __restrict__ w2, const float* __restrict__ b2,
                               float* __restrict__ hout, int zblocks) {
    if ((int)blockIdx.x < zblocks) {
        int i = blockIdx.x * blockDim.x + threadIdx.x;
        if (i < NN) g_cursor[i] = 0;
        return;
    }
    __shared__ float sw1[16 * HH], sb1[HH], sw2[HH * 16], sb2[16];
    for (int i = threadIdx.x; i < 16 * HH; i += blockDim.x) { sw1[i] = w1[i]; sw2[i] = w2[i]; }
    for (int i = threadIdx.x; i < HH; i += blockDim.x) sb1[i] = b1[i];
    if (threadIdx.x < 16) sb2[threadIdx.x] = b2[threadIdx.x];
    __syncthreads();
    int v = (blockIdx.x - zblocks) * blockDim.x + threadIdx.x;
    if (v >= NN) return;
    float m[16], out[16];
#pragma unroll
    for (int i = 0; i < 16; i++) m[i] = mask[v * 16 + i];
#pragma unroll
    for (int o = 0; o < 16; o++) out[o] = sb2[o];
#pragma unroll 4
    for (int j = 0; j < HH; j++) {
        float a = sb1[j];
#pragma unroll
        for (int i = 0; i < 16; i++) a = fmaf(m[i], sw1[i * HH + j], a);
        a = fmaxf(a, 0.f);
#pragma unroll
        for (int o = 0; o < 16; o++) out[o] = fmaf(a, sw2[j * 16 + o], out[o]);
    }
#pragma unroll
    for (int o = 0; o < 16; o++) hout[v * 16 + o] = out[o] + x[v * 16 + o];
}

__global__ void k_count(const int* __restrict__ ei) {
    int e = blockIdx.x * blockDim.x + threadIdx.x;
    if (e >= E2) return;
    int d = (e < EE) ? ei[e + EE] : ei[e - EE];
    atomicAdd(&g_cursor[d], 1);
}

// 20 blocks x 1000; per-block exclusive scan; zero cursor; compute deg/dis
__global__ void k_scanA() {
    __shared__ int s[1024];
    int tid = threadIdx.x;
    int i = blockIdx.x * 1000 + tid;
    bool ok = (tid < 1000 && i < NN);
    int v = ok ? g_cursor[i] : 0;
    if (ok) {
        g_cursor[i] = 0;
        float df = (float)v;
        g_degf[i] = df;
        g_dis[i] = v > 0 ? rsqrtf(df) : 0.f;
    }
    s[tid] = v;
    __syncthreads();
    for (int off = 1; off < 1024; off <<= 1) {
        int t = (tid >= off) ? s[tid - off] : 0;
        __syncthreads();
        s[tid] += t;
        __syncthreads();
    }
    if (ok) g_rowptr[i] = s[tid] - v;
    if (tid == 1023) g_blocksum[blockIdx.x] = s[1023];
}

__global__ void k_scanB() {
    int b = blockIdx.x;
    int off = 0, tot = 0;
#pragma unroll
    for (int k = 0; k < 20; k++) {
        int bs = g_blocksum[k];
        if (k < b) off += bs;
        tot += bs;
    }
    int i = b * 1000 + threadIdx.x;
    if (threadIdx.x < 1000 && i < NN) g_rowptr[i] += off;
    if (b == 19 && threadIdx.x == 0) g_rowptr[NN] = tot;
}

__global__ void k_fill(const int* __restrict__ ei) {
    int e = blockIdx.x * blockDim.x + threadIdx.x;
    if (e >= E2) return;
    int srow, d, er;
    if (e < EE) { srow = ei[e]; d = ei[e + EE]; er = e; }
    else        { srow = ei[e]; d = ei[e - EE]; er = e - EE; }
    int idx = g_rowptr[d] + atomicAdd(&g_cursor[d], 1);
    float nrm = g_dis[srow] * g_dis[d];
    g_csr[idx] = make_int4(srow, er, __float_as_int(nrm), 0);
}

// ---------------- tile-MM core: 32-node tile, 16 warps, 2 nodes/warp ----------------
__device__ __forceinline__ void mm_tile(const float* __restrict__ sw, const float* __restrict__ sh,
                                        const float* __restrict__ Cin, float* __restrict__ Cout,
                                        int F, int flags, const float* __restrict__ bias,
                                        int vbase, int w, int lane) {
    ull acc[2][2];
#pragma unroll
    for (int i = 0; i < 2; i++) { acc[i][0] = 0ull; acc[i][1] = 0ull; }
    const float* h0 = &sh[(w * 2 + 0) * F];
    const float* h1 = &sh[(w * 2 + 1) * F];
    for (int j4 = 0; j4 < F; j4 += 4) {
        float4 hv0 = *(const float4*)&h0[j4];
        float4 hv1 = *(const float4*)&h1[j4];
#pragma unroll
        for (int jj = 0; jj < 4; jj++) {
            ulonglong2 wv = *(const ulonglong2*)&sw[(j4 + jj) * HH + lane * 4];
            float f0 = jj == 0 ? hv0.x : jj == 1 ? hv0.y : jj == 2 ? hv0.z : hv0.w;
            float f1 = jj == 0 ? hv1.x : jj == 1 ? hv1.y : jj == 2 ? hv1.z : hv1.w;
            ull a0 = pk2(f0), a1 = pk2(f1);
            acc[0][0] = fma2(a0, wv.x, acc[0][0]); acc[0][1] = fma2(a0, wv.y, acc[0][1]);
            acc[1][0] = fma2(a1, wv.x, acc[1][0]); acc[1][1] = fma2(a1, wv.y, acc[1][1]);
        }
    }
    int o = lane * 4;
#pragma unroll
    for (int i = 0; i < 2; i++) {
        int v = vbase + w * 2 + i;
        float4 r;
        upk(acc[i][0], r.x, r.y);
        upk(acc[i][1], r.z, r.w);
        if (flags & MM_BIAS) {
            r.x += bias[o]; r.y += bias[o + 1]; r.z += bias[o + 2]; r.w += bias[o + 3];
        }
        if (flags & MM_BIASDEG) {
            float dg = g_degf[v];
            r.x += dg * bias[o]; r.y += dg * bias[o + 1];
            r.z += dg * bias[o + 2]; r.w += dg * bias[o + 3];
        }
        if (flags & MM_ACC) {
            float4 c = *(const float4*)&Cin[v * HH + o];
            r.x += c.x; r.y += c.y; r.z += c.z; r.w += c.w;
        }
        if (flags & MM_RELU) {
            r.x = fmaxf(r.x, 0.f); r.y = fmaxf(r.y, 0.f);
            r.z = fmaxf(r.z, 0.f); r.w = fmaxf(r.w, 0.f);
        }
        *(float4*)&Cout[v * HH + o] = r;
    }
}

__device__ __forceinline__ void load_w(const float* __restrict__ W, float* __restrict__ sw,
                                       int n, int tid) {
    for (int i = tid * 4; i < n; i += TB2 * 4)
        *(float4*)&sw[i] = *(const float4*)&W[i];
}

__device__ __forceinline__ void load_tile(const float* __restrict__ A, float* __restrict__ sh,
                                          int vbase, int F, int tid) {
    for (int i = tid * 4; i < TILE * F; i += TB2 * 4)
        *(float4*)&sh[i] = *(const float4*)&A[vbase * F + i];
}

// ---------------- plain tiled matmul ----------------
__global__ void __launch_bounds__(TB2, 2)
k_mm(const float* __restrict__ A, const float* __restrict__ W,
     const float* __restrict__ Cin, float* __restrict__ Cout,
     int F, int flags, const float* __restrict__ bias) {
    extern __shared__ float sm[];
    float* sw = sm;
    float* sh = sm + F * HH;
    int tid = threadIdx.x;
    load_w(W, sw, F * HH, tid);
    int vbase = blockIdx.x * TILE;
    load_tile(A, sh, vbase, F, tid);
    __syncthreads();
    mm_tile(sw, sh, Cin, Cout, F, flags, bias, vbase, tid >> 5, tid & 31);
}

// ---------------- dual matmul: blockIdx.y picks half ----------------
__global__ void __launch_bounds__(TB2, 2)
k_mm2(const float* __restrict__ A, const float* __restrict__ Wbase,
      float* __restrict__ C0, float* __restrict__ C1, int F) {
    extern __shared__ float sm[];
    float* sw = sm;
    float* sh = sm + F * HH;
    int tid = threadIdx.x;
    const float* W = Wbase + blockIdx.y * F * HH;
    float* Cout = blockIdx.y ? C1 : C0;
    load_w(W, sw, F * HH, tid);
    int vbase = blockIdx.x * TILE;
    load_tile(A, sh, vbase, F, tid);
    __syncthreads();
    mm_tile(sw, sh, nullptr, Cout, F, 0, nullptr, vbase, tid >> 5, tid & 31);
}

// ---------------- fused prop + matmul (6-edge software pipeline, 2 nodes/warp) ----------------
__global__ void __launch_bounds__(TB2, 2)
k_propmm(const float* __restrict__ tin, float* __restrict__ tout,
         const float* __restrict__ W,
         const float* __restrict__ Cin, float* __restrict__ Cout,
         int flags, const float* __restrict__ bias, int write_t) {
    extern __shared__ float sm[];
    float* sw = sm;              // 128*128
    float* st = sm + HH * HH;    // 32*128
    int tid = threadIdx.x;
    load_w(W, sw, HH * HH, tid);
    int w = tid >> 5, lane = tid & 31;
    int jo = lane * 4;
    int vbase = blockIdx.x * TILE;
#pragma unroll
    for (int i = 0; i < 2; i++) {
        int d = vbase + w * 2 + i;
        int beg = g_rowptr[d], end = g_rowptr[d + 1];
        float a0 = 0.f, a1 = 0.f, a2 = 0.f, a3 = 0.f;
        int idx = beg;
        for (; idx + 6 <= end; idx += 6) {
            int4 c0 = g_csr[idx + 0];
            int4 c1 = g_csr[idx + 1];
            int4 c2 = g_csr[idx + 2];
            int4 c3 = g_csr[idx + 3];
            int4 c4 = g_csr[idx + 4];
            int4 c5 = g_csr[idx + 5];
            float4 t0 = *(const float4*)&tin[c0.x * HH + jo];
            float4 t1 = *(const float4*)&tin[c1.x * HH + jo];
            float4 t2 = *(const float4*)&tin[c2.x * HH + jo];
            float4 t3 = *(const float4*)&tin[c3.x * HH + jo];
            float4 t4 = *(const float4*)&tin[c4.x * HH + jo];
            float4 t5 = *(const float4*)&tin[c5.x * HH + jo];
            float n0 = __int_as_float(c0.z), n1 = __int_as_float(c1.z);
            float n2 = __int_as_float(c2.z), n3 = __int_as_float(c3.z);
            float n4 = __int_as_float(c4.z), n5 = __int_as_float(c5.z);
            a0 = fmaf(n0, t0.x, a0); a1 = fmaf(n0, t0.y, a1);
            a2 = fmaf(n0, t0.z, a2); a3 = fmaf(n0, t0.w, a3);
            a0 = fmaf(n1, t1.x, a0); a1 = fmaf(n1, t1.y, a1);
            a2 = fmaf(n1, t1.z, a2); a3 = fmaf(n1, t1.w, a3);
            a0 = fmaf(n2, t2.x, a0); a1 = fmaf(n2, t2.y, a1);
            a2 = fmaf(n2, t2.z, a2); a3 = fmaf(n2, t2.w, a3);
            a0 = fmaf(n3, t3.x, a0); a1 = fmaf(n3, t3.y, a1);
            a2 = fmaf(n3, t3.z, a2); a3 = fmaf(n3, t3.w, a3);
            a0 = fmaf(n4, t4.x, a0); a1 = fmaf(n4, t4.y, a1);
            a2 = fmaf(n4, t4.z, a2); a3 = fmaf(n4, t4.w, a3);
            a0 = fmaf(n5, t5.x, a0); a1 = fmaf(n5, t5.y, a1);
            a2 = fmaf(n5, t5.z, a2); a3 = fmaf(n5, t5.w, a3);
        }
        for (; idx < end; idx++) {
            int4 c = g_csr[idx];
            float nrm = __int_as_float(c.z);
            float4 t = *(const float4*)&tin[c.x * HH + jo];
            a0 = fmaf(nrm, t.x, a0); a1 = fmaf(nrm, t.y, a1);
            a2 = fmaf(nrm, t.z, a2); a3 = fmaf(nrm, t.w, a3);
        }
        float4 r = make_float4(a0, a1, a2, a3);
        *(float4*)&st[(w * 2 + i) * HH + jo] = r;
        if (write_t) *(float4*)&tout[d * HH + jo] = r;
    }
    __syncthreads();
    mm_tile(sw, st, Cin, Cout, HH, flags, bias, vbase, w, lane);
}

// ---------------- EA gather core (2-edge software pipeline) ----------------
__device__ __forceinline__ void ea_gather_node(int d, int jo, int lane,
                                               const float* __restrict__ eattr,
                                               const float* __restrict__ sw1,
                                               const float* __restrict__ sb1,
                                               float& a0, float& a1, float& a2, float& a3) {
    int beg = g_rowptr[d], end = g_rowptr[d + 1];
    float4 ad = *(const float4*)&g_adst[d * HH + jo];
    ull zb0 = pkxy(ad.x + sb1[jo], ad.y + sb1[jo + 1]);
    ull zb1 = pkxy(ad.z + sb1[jo + 2], ad.w + sb1[jo + 3]);
    a0 = a1 = a2 = a3 = 0.f;
    int idx = beg;
    for (; idx + 2 <= end; idx += 2) {
        int4 c0 = g_csr[idx];
        int4 c1 = g_csr[idx + 1];
        float ea0 = (lane < 16) ? eattr[c0.y * 16 + lane] : 0.f;
        float ea1 = (lane < 16) ? eattr[c1.y * 16 + lane] : 0.f;
        ulonglong2 as0 = *(const ulonglong2*)&g_asrc[c0.x * HH + jo];
        ulonglong2 as1 = *(const ulonglong2*)&g_asrc[c1.x * HH + jo];
        ull z00 = add2(zb0, as0.x), z01 = add2(zb1, as0.y);
        ull z10 = add2(zb0, as1.x), z11 = add2(zb1, as1.y);
#pragma unroll
        for (int q = 0; q < 16; q++) {
            float aq0 = __shfl_sync(0xffffffffu, ea0, q);
            float aq1 = __shfl_sync(0xffffffffu, ea1, q);
            ulonglong2 wv = *(const ulonglong2*)&sw1[q * HH + jo];
            ull p0 = pk2(aq0), p1 = pk2(aq1);
            z00 = fma2(p0, wv.x, z00); z01 = fma2(p0, wv.y, z01);
            z10 = fma2(p1, wv.x, z10); z11 = fma2(p1, wv.y, z11);
        }
        float f0, f1, f2, f3, g0, g1, g2, g3;
        upk(z00, f0, f1); upk(z01, f2, f3);
        upk(z10, g0, g1); upk(z11, g2, g3);
        a0 += fmaxf(f0, 0.f) + fmaxf(g0, 0.f);
        a1 += fmaxf(f1, 0.f) + fmaxf(g1, 0.f);
        a2 += fmaxf(f2, 0.f) + fmaxf(g2, 0.f);
        a3 += fmaxf(f3, 0.f) + fmaxf(g3, 0.f);
    }
    for (; idx < end; idx++) {
        int4 c = g_csr[idx];
        float eav = (lane < 16) ? eattr[c.y * 16 + lane] : 0.f;
        ulonglong2 as = *(const ulonglong2*)&g_asrc[c.x * HH + jo];
        ull z0 = add2(zb0, as.x);
        ull z1 = add2(zb1, as.y);
#pragma unroll
        for (int q = 0; q < 16; q++) {
            float a = __shfl_sync(0xffffffffu, eav, q);
            ull ap = pk2(a);
            ulonglong2 wv = *(const ulonglong2*)&sw1[q * HH + jo];
            z0 = fma2(ap, wv.x, z0);
            z1 = fma2(ap, wv.y, z1);
        }
        float f0, f1, f2, f3;
        upk(z0, f0, f1);
        upk(z1, f2, f3);
        a0 += fmaxf(f0, 0.f); a1 += fmaxf(f1, 0.f);
        a2 += fmaxf(f2, 0.f); a3 += fmaxf(f3, 0.f);
    }
}

// ---------------- fused EA gather + w2 projection (2 nodes/warp) ----------------
__global__ void __launch_bounds__(TB2, 2)
k_eagmm(const float* __restrict__ eattr,
        const float* __restrict__ w1ea, const float* __restrict__ b1,
        const float* __restrict__ w2, const float* __restrict__ b2,
        float* __restrict__ Cout) {
    extern __shared__ float sm[];
    float* sw2 = sm;               // 128*128
    float* st = sw2 + HH * HH;     // 32*128
    float* sw1 = st + TILE * HH;   // 16*128
    float* sb1 = sw1 + 16 * HH;    // 128
    int tid = threadIdx.x;
    load_w(w2, sw2, HH * HH, tid);
    for (int i = tid; i < 16 * HH; i += TB2) sw1[i] = w1ea[i];
    for (int i = tid; i < HH; i += TB2) sb1[i] = b1[i];
    int w = tid >> 5, lane = tid & 31;
    int jo = lane * 4;
    int vbase = blockIdx.x * TILE;
    __syncthreads();
#pragma unroll
    for (int i = 0; i < 2; i++) {
        int d = vbase + w * 2 + i;
        float a0, a1, a2, a3;
        ea_gather_node(d, jo, lane, eattr, sw1, sb1, a0, a1, a2, a3);
        *(float4*)&st[(w * 2 + i) * HH + jo] = make_float4(a0, a1, a2, a3);
    }
    __syncthreads();
    mm_tile(sw2, st, nullptr, Cout, HH, MM_RELU | MM_BIASDEG, b2, vbase, w, lane);
}

// ---------------- EA2: gather + O=16 projection -> d_out ----------------
__global__ void k_ea_gather16(const float* __restrict__ eattr,
                              const float* __restrict__ w1ea, const float* __restrict__ b1,
                              const float* __restrict__ w2, const float* __restrict__ b2,
                              float* __restrict__ out) {
    extern __shared__ float sm[];
    float* sw1 = sm;             // 16*128
    float* sb1 = sm + 16 * HH;   // 128
    float* sw2t = sb1 + HH;      // 16*128 transposed
    float* sb2 = sw2t + HH * 16;
    float* buf = sb2 + 16;       // 8*128
    int tid = threadIdx.x;
    for (int i = tid; i < 16 * HH; i += blockDim.x) sw1[i] = w1ea[i];
    for (int i = tid; i < HH; i += blockDim.x) sb1[i] = b1[i];
    for (int i = tid; i < HH * 16; i += blockDim.x) {
        int j = i >> 4, o = i & 15;
        sw2t[o * HH + j] = w2[i];
    }
    if (tid < 16) sb2[tid] = b2[tid];
    __syncthreads();

    int w = tid >> 5, lane = tid & 31;
    int jo = lane * 4;
    for (int d = blockIdx.x * 8 + w; d < NN; d += gridDim.x * 8) {
        float a0, a1, a2, a3;
        ea_gather_node(d, jo, lane, eattr, sw1, sb1, a0, a1, a2, a3);
        *(float4*)&buf[w * HH + jo] = make_float4(a0, a1, a2, a3);
        __syncwarp();
        if (lane < 16) {
            int o = lane;
            float acc = g_degf[d] * sb2[o];
            for (int j4 = 0; j4 < HH; j4 += 4) {
                float4 b = *(const float4*)&buf[w * HH + j4];
                float4 wv = *(const float4*)&sw2t[o * HH + j4];
                acc = fmaf(b.x, wv.x, acc); acc = fmaf(b.y, wv.y, acc);
                acc = fmaf(b.z, wv.z, acc); acc = fmaf(b.w, wv.w, acc);
            }
            out[d * 16 + o] = acc;
        }
        __syncwarp();
    }
}

// ---------------- host ----------------
extern "C" void kernel_launch(void* const* d_in, const int* in_sizes, int n_in,
                              void* d_out, int out_size) {
    int eidx, wb;
    if (in_sizes[3] == 2 * EE) { eidx = 3; wb = 4; }
    else                       { eidx = n_in - 1; wb = 3; }

    const float* x     = (const float*)d_in[0];
    const float* mask  = (const float*)d_in[1];
    const float* eattr = (const float*)d_in[2];
    const int*   ei    = (const int*)d_in[eidx];
    const float* m_w1   = (const float*)d_in[wb + 0];
    const float* m_b1   = (const float*)d_in[wb + 1];
    const float* m_w2   = (const float*)d_in[wb + 2];
    const float* m_b2   = (const float*)d_in[wb + 3];
    const float* ea0_w1 = (const float*)d_in[wb + 4];
    const float* ea0_b1 = (const float*)d_in[wb + 5];
    const float* ea0_w2 = (const float*)d_in[wb + 6];
    const float* ea0_b2 = (const float*)d_in[wb + 7];
    const float* tag0_w = (const float*)d_in[wb + 8];
    const float* tag0_b = (const float*)d_in[wb + 9];
    const float* ea1_w1 = (const float*)d_in[wb + 10];
    const float* ea1_b1 = (const float*)d_in[wb + 11];
    const float* ea1_w2 = (const float*)d_in[wb + 12];
    const float* ea1_b2 = (const float*)d_in[wb + 13];
    const float* tag1_w = (const float*)d_in[wb + 14];
    const float* tag1_b = (const float*)d_in[wb + 15];
    const float* ea2_w1 = (const float*)d_in[wb + 16];
    const float* ea2_b1 = (const float*)d_in[wb + 17];
    const float* ea2_w2 = (const float*)d_in[wb + 18];
    const float* ea2_b2 = (const float*)d_in[wb + 19];

    float *p_h, *p_adst, *p_asrc, *p_t1, *p_t2, *p_out;
    cudaGetSymbolAddress((void**)&p_h, g_h);
    cudaGetSymbolAddress((void**)&p_adst, g_adst);
    cudaGetSymbolAddress((void**)&p_asrc, g_asrc);
    cudaGetSymbolAddress((void**)&p_t1, g_t1);
    cudaGetSymbolAddress((void**)&p_t2, g_t2);
    cudaGetSymbolAddress((void**)&p_out, g_out);

    static bool attr_done = false;
    if (!attr_done) {
        cudaFuncSetAttribute(k_mm, cudaFuncAttributeMaxDynamicSharedMemorySize, 90 * 1024);
        cudaFuncSetAttribute(k_mm2, cudaFuncAttributeMaxDynamicSharedMemorySize, 90 * 1024);
        cudaFuncSetAttribute(k_propmm, cudaFuncAttributeMaxDynamicSharedMemorySize, 90 * 1024);
        cudaFuncSetAttribute(k_eagmm, cudaFuncAttributeMaxDynamicSharedMemorySize, 96 * 1024);
        cudaFuncSetAttribute(k_ea_gather16, cudaFuncAttributeMaxDynamicSharedMemorySize, 48 * 1024);
        attr_done = true;
    }

    const int TB = 256;
    const int gN = (NN + TB - 1) / TB;   // 79
    const int gE = (E2 + TB - 1) / TB;
    const int gW = 2500;
    const size_t smm128 = (size_t)(HH * HH + TILE * HH) * 4;                 // 80KB
    const size_t smm16  = (size_t)(16 * HH + TILE * 16) * 4;                 // 10KB
    const size_t sgm    = (size_t)(HH * HH + TILE * HH + 16 * HH + HH) * 4;  // ~88.5KB
    const size_t sga16  = (size_t)(16 * HH + HH + HH * 16 + 16 + 8 * HH) * 4;

    // CSR + mask MLP
    k_zero_maskmlp<<<2 * gN, TB>>>(x, mask, m_w1, m_b1, m_w2, m_b2, p_h, gN);
    k_count<<<gE, TB>>>(ei);
    k_scanA<<<20, 1024>>>();
    k_scanB<<<20, 1024>>>();
    k_fill<<<gE, TB>>>(ei);

    // ---- EA0 (F=16) ----
    k_mm2<<<dim3(NT, 2), TB2, smm16>>>(p_h, ea0_w1, p_adst, p_asrc, 16);
    k_eagmm<<<NT, TB2, sgm>>>(eattr, ea0_w1 + 2 * 16 * HH, ea0_b1, ea0_w2, ea0_b2, p_h);

    // ---- TAG0 ----
    k_mm<<<NT, TB2, smm128>>>(p_h, tag0_w, nullptr, p_out, HH, 0, nullptr);
    k_propmm<<<NT, TB2, smm128>>>(p_h, p_t1, tag0_w + 1 * HH * HH, p_out, p_out,
                                  MM_ACC, nullptr, 1);
    k_propmm<<<NT, TB2, smm128>>>(p_t1, p_t2, tag0_w + 2 * HH * HH, p_out, p_out,
                                  MM_ACC, nullptr, 1);
    k_propmm<<<NT, TB2, smm128>>>(p_t2, nullptr, tag0_w + 3 * HH * HH, p_out, p_h,
                                  MM_ACC | MM_RELU | MM_BIAS, tag0_b, 0);

    // ---- EA1 (F=128) ----
    k_mm2<<<dim3(NT, 2), TB2, smm128>>>(p_h, ea1_w1, p_adst, p_asrc, HH);
    k_eagmm<<<NT, TB2, sgm>>>(eattr, ea1_w1 + 2 * HH * HH, ea1_b1, ea1_w2, ea1_b2, p_h);

    // ---- TAG1 ----
    k_mm<<<NT, TB2, smm128>>>(p_h, tag1_w, nullptr, p_out, HH, 0, nullptr);
    k_propmm<<<NT, TB2, smm128>>>(p_h, p_t1, tag1_w + 1 * HH * HH, p_out, p_out,
                                  MM_ACC, nullptr, 1);
    k_propmm<<<NT, TB2, smm128>>>(p_t1, p_t2, tag1_w + 2 * HH * HH, p_out, p_out,
                                  MM_ACC, nullptr, 1);
    k_propmm<<<NT, TB2, smm128>>>(p_t2, nullptr, tag1_w + 3 * HH * HH, p_out, p_h,
                                  MM_ACC | MM_RELU | MM_BIAS, tag1_b, 0);

    // ---- EA2 (F=128, OUT=16, no relu) -> d_out ----
    k_mm2<<<dim3(NT, 2), TB2, smm128>>>(p_h, ea2_w1, p_adst, p_asrc, HH);
    k_ea_gather16<<<gW, TB, sga16>>>(eattr, ea2_w1 + 2 * HH * HH, ea2_b1,
                                     ea2_w2, ea2_b2, (float*)d_out);
}

// round 14
// speedup vs baseline: 1.1854x; 1.1854x over previous
#include <cuda_runtime.h>
#include <cuda_fp16.h>

#define NN 20000
#define EE 160000
#define E2 320000
#define HH 128
#define TILE 64
#define NT ((NN + TILE - 1) / TILE)   // 313
#define TB2 512

#define MM_ACC 1
#define MM_RELU 2
#define MM_BIAS 4
#define MM_BIASDEG 8

typedef unsigned long long ull;

__device__ __forceinline__ ull pk2(float x) {
    ull r; asm("mov.b64 %0,{%1,%1};" : "=l"(r) : "f"(x)); return r;
}
__device__ __forceinline__ ull pkxy(float x, float y) {
    ull r; asm("mov.b64 %0,{%1,%2};" : "=l"(r) : "f"(x), "f"(y)); return r;
}
__device__ __forceinline__ ull fma2(ull a, ull b, ull c) {
    ull d; asm("fma.rn.f32x2 %0,%1,%2,%3;" : "=l"(d) : "l"(a), "l"(b), "l"(c)); return d;
}
__device__ __forceinline__ ull add2(ull a, ull b) {
    ull d; asm("add.rn.f32x2 %0,%1,%2;" : "=l"(d) : "l"(a), "l"(b)); return d;
}
__device__ __forceinline__ void upk(ull v, float& x, float& y) {
    asm("mov.b64 {%0,%1},%2;" : "=f"(x), "=f"(y) : "l"(v));
}

// ---------------- scratch ----------------
__device__ float g_h[NN * HH];
__device__ float g_adst[NN * HH];
__device__ float g_asrc[NN * HH];
__device__ float g_out[NN * HH];
__device__ __half2 g_t16a[NN * 64];   // fp16 TAG intermediates
__device__ __half2 g_t16b[NN * 64];
__device__ float g_dis[NN];
__device__ float g_degf[NN];
__device__ int g_rowptr[NN + 1];
__device__ int g_cursor[NN];
__device__ int g_blocksum[32];
__device__ int4 g_csr[E2];   // (src, ea_row, bitcast(norm), 0)

// ---------------- fused: zero cursor + mask MLP ----------------
__global__ void k_zero_maskmlp(const float* __restrict__ x, const float* __restrict__ mask,
                               const float* __restrict__ w1, const float* __restrict__ b1,
                               const float* __restrict__ w2, const float* __restrict__ b2,
                               float* __restrict__ hout, int zblocks) {
    if ((int)blockIdx.x < zblocks) {
        int i = blockIdx.x * blockDim.x + threadIdx.x;
        if (i < NN) g_cursor[i] = 0;
        return;
    }
    __shared__ float sw1[16 * HH], sb1[HH], sw2[HH * 16], sb2[16];
    for (int i = threadIdx.x; i < 16 * HH; i += blockDim.x) { sw1[i] = w1[i]; sw2[i] = w2[i]; }
    for (int i = threadIdx.x; i < HH; i += blockDim.x) sb1[i] = b1[i];
    if (threadIdx.x < 16) sb2[threadIdx.x] = b2[threadIdx.x];
    __syncthreads();
    int v = (blockIdx.x - zblocks) * blockDim.x + threadIdx.x;
    if (v >= NN) return;
    float m[16], out[16];
#pragma unroll
    for (int i = 0; i < 16; i++) m[i] = mask[v * 16 + i];
#pragma unroll
    for (int o = 0; o < 16; o++) out[o] = sb2[o];
#pragma unroll 4
    for (int j = 0; j < HH; j++) {
        float a = sb1[j];
#pragma unroll
        for (int i = 0; i < 16; i++) a = fmaf(m[i], sw1[i * HH + j], a);
        a = fmaxf(a, 0.f);
#pragma unroll
        for (int o = 0; o < 16; o++) out[o] = fmaf(a, sw2[j * 16 + o], out[o]);
    }
#pragma unroll
    for (int o = 0; o < 16; o++) hout[v * 16 + o] = out[o] + x[v * 16 + o];
}

__global__ void k_count(const int* __restrict__ ei) {
    int e = blockIdx.x * blockDim.x + threadIdx.x;
    if (e >= E2) return;
    int d = (e < EE) ? ei[e + EE] : ei[e - EE];
    atomicAdd(&g_cursor[d], 1);
}

// 20 blocks x 1000; per-block exclusive scan; zero cursor; compute deg/dis
__global__ void k_scanA() {
    __shared__ int s[1024];
    int tid = threadIdx.x;
    int i = blockIdx.x * 1000 + tid;
    bool ok = (tid < 1000 && i < NN);
    int v = ok ? g_cursor[i] : 0;
    if (ok) {
        g_cursor[i] = 0;
        float df = (float)v;
        g_degf[i] = df;
        g_dis[i] = v > 0 ? rsqrtf(df) : 0.f;
    }
    s[tid] = v;
    __syncthreads();
    for (int off = 1; off < 1024; off <<= 1) {
        int t = (tid >= off) ? s[tid - off] : 0;
        __syncthreads();
        s[tid] += t;
        __syncthreads();
    }
    if (ok) g_rowptr[i] = s[tid] - v;
    if (tid == 1023) g_blocksum[blockIdx.x] = s[1023];
}

__global__ void k_scanB() {
    int b = blockIdx.x;
    int off = 0, tot = 0;
#pragma unroll
    for (int k = 0; k < 20; k++) {
        int bs = g_blocksum[k];
        if (k < b) off += bs;
        tot += bs;
    }
    int i = b * 1000 + threadIdx.x;
    if (threadIdx.x < 1000 && i < NN) g_rowptr[i] += off;
    if (b == 19 && threadIdx.x == 0) g_rowptr[NN] = tot;
}

__global__ void k_fill(const int* __restrict__ ei) {
    int e = blockIdx.x * blockDim.x + threadIdx.x;
    if (e >= E2) return;
    int srow, d, er;
    if (e < EE) { srow = ei[e]; d = ei[e + EE]; er = e; }
    else        { srow = ei[e]; d = ei[e - EE]; er = e - EE; }
    int idx = g_rowptr[d] + atomicAdd(&g_cursor[d], 1);
    float nrm = g_dis[srow] * g_dis[d];
    g_csr[idx] = make_int4(srow, er, __float_as_int(nrm), 0);
}

// ---------------- tile-MM core: 64-node tile, 16 warps, 4 nodes/warp ----------------
__device__ __forceinline__ void mm_tile(const float* __restrict__ sw, const float* __restrict__ sh,
                                        const float* __restrict__ Cin, float* __restrict__ Cout,
                                        int F, int flags, const float* __restrict__ bias,
                                        int vbase, int w, int lane) {
    ull acc[4][2];
#pragma unroll
    for (int i = 0; i < 4; i++) { acc[i][0] = 0ull; acc[i][1] = 0ull; }
    const float* h0 = &sh[(w * 4 + 0) * F];
    const float* h1 = &sh[(w * 4 + 1) * F];
    const float* h2 = &sh[(w * 4 + 2) * F];
    const float* h3 = &sh[(w * 4 + 3) * F];
    for (int j4 = 0; j4 < F; j4 += 4) {
        float4 hv0 = *(const float4*)&h0[j4];
        float4 hv1 = *(const float4*)&h1[j4];
        float4 hv2 = *(const float4*)&h2[j4];
        float4 hv3 = *(const float4*)&h3[j4];
#pragma unroll
        for (int jj = 0; jj < 4; jj++) {
            ulonglong2 wv = *(const ulonglong2*)&sw[(j4 + jj) * HH + lane * 4];
            float f0 = jj == 0 ? hv0.x : jj == 1 ? hv0.y : jj == 2 ? hv0.z : hv0.w;
            float f1 = jj == 0 ? hv1.x : jj == 1 ? hv1.y : jj == 2 ? hv1.z : hv1.w;
            float f2 = jj == 0 ? hv2.x : jj == 1 ? hv2.y : jj == 2 ? hv2.z : hv2.w;
            float f3 = jj == 0 ? hv3.x : jj == 1 ? hv3.y : jj == 2 ? hv3.z : hv3.w;
            ull a0 = pk2(f0), a1 = pk2(f1), a2 = pk2(f2), a3 = pk2(f3);
            acc[0][0] = fma2(a0, wv.x, acc[0][0]); acc[0][1] = fma2(a0, wv.y, acc[0][1]);
            acc[1][0] = fma2(a1, wv.x, acc[1][0]); acc[1][1] = fma2(a1, wv.y, acc[1][1]);
            acc[2][0] = fma2(a2, wv.x, acc[2][0]); acc[2][1] = fma2(a2, wv.y, acc[2][1]);
            acc[3][0] = fma2(a3, wv.x, acc[3][0]); acc[3][1] = fma2(a3, wv.y, acc[3][1]);
        }
    }
    int o = lane * 4;
#pragma unroll
    for (int i = 0; i < 4; i++) {
        int v = vbase + w * 4 + i;
        if (v >= NN) continue;
        float4 r;
        upk(acc[i][0], r.x, r.y);
        upk(acc[i][1], r.z, r.w);
        if (flags & MM_BIAS) {
            r.x += bias[o]; r.y += bias[o + 1]; r.z += bias[o + 2]; r.w += bias[o + 3];
        }
        if (flags & MM_BIASDEG) {
            float dg = g_degf[v];
            r.x += dg * bias[o]; r.y += dg * bias[o + 1];
            r.z += dg * bias[o + 2]; r.w += dg * bias[o + 3];
        }
        if (flags & MM_ACC) {
            float4 c = *(const float4*)&Cin[v * HH + o];
            r.x += c.x; r.y += c.y; r.z += c.z; r.w += c.w;
        }
        if (flags & MM_RELU) {
            r.x = fmaxf(r.x, 0.f); r.y = fmaxf(r.y, 0.f);
            r.z = fmaxf(r.z, 0.f); r.w = fmaxf(r.w, 0.f);
        }
        *(float4*)&Cout[v * HH + o] = r;
    }
}

__device__ __forceinline__ void load_w(const float* __restrict__ W, float* __restrict__ sw,
                                       int n, int tid) {
    for (int i = tid * 4; i < n; i += TB2 * 4)
        *(float4*)&sw[i] = *(const float4*)&W[i];
}

__device__ __forceinline__ void load_tile(const float* __restrict__ A, float* __restrict__ sh,
                                          int vbase, int F, int tid) {
    for (int i = tid * 4; i < TILE * F; i += TB2 * 4) {
        int g = vbase * F + i;
        float4 v = (g < NN * F) ? *(const float4*)&A[g] : make_float4(0.f, 0.f, 0.f, 0.f);
        *(float4*)&sh[i] = v;
    }
}

// ---------------- plain tiled matmul ----------------
__global__ void __launch_bounds__(TB2, 2)
k_mm(const float* __restrict__ A, const float* __restrict__ W,
     const float* __restrict__ Cin, float* __restrict__ Cout,
     int F, int flags, const float* __restrict__ bias) {
    extern __shared__ float sm[];
    float* sw = sm;
    float* sh = sm + F * HH;
    int tid = threadIdx.x;
    load_w(W, sw, F * HH, tid);
    int vbase = blockIdx.x * TILE;
    load_tile(A, sh, vbase, F, tid);
    __syncthreads();
    mm_tile(sw, sh, Cin, Cout, F, flags, bias, vbase, tid >> 5, tid & 31);
}

// ---------------- dual matmul: blockIdx.y picks half ----------------
__global__ void __launch_bounds__(TB2, 2)
k_mm2(const float* __restrict__ A, const float* __restrict__ Wbase,
      float* __restrict__ C0, float* __restrict__ C1, int F) {
    extern __shared__ float sm[];
    float* sw = sm;
    float* sh = sm + F * HH;
    int tid = threadIdx.x;
    const float* W = Wbase + blockIdx.y * F * HH;
    float* Cout = blockIdx.y ? C1 : C0;
    load_w(W, sw, F * HH, tid);
    int vbase = blockIdx.x * TILE;
    load_tile(A, sh, vbase, F, tid);
    __syncthreads();
    mm_tile(sw, sh, nullptr, Cout, F, 0, nullptr, vbase, tid >> 5, tid & 31);
}

// ---------------- fused prop + matmul (6-edge pipeline; fp32 or fp16 input) ----------------
// tin32 != null: gather fp32 rows. else gather fp16 rows from tin16.
// tout16 != null: write propagated t in fp16.
__global__ void __launch_bounds__(TB2, 2)
k_propmm(const float* __restrict__ tin32, const __half2* __restrict__ tin16,
         __half2* __restrict__ tout16,
         const float* __restrict__ W,
         const float* __restrict__ Cin, float* __restrict__ Cout,
         int flags, const float* __restrict__ bias) {
    extern __shared__ float sm[];
    float* sw = sm;              // 128*128
    float* st = sm + HH * HH;    // 64*128
    int tid = threadIdx.x;
    load_w(W, sw, HH * HH, tid);
    int w = tid >> 5, lane = tid & 31;
    int jo = lane * 4;
    int vbase = blockIdx.x * TILE;
#pragma unroll
    for (int i = 0; i < 4; i++) {
        int d = vbase + w * 4 + i;
        if (d >= NN) {
            *(float4*)&st[(w * 4 + i) * HH + jo] = make_float4(0.f, 0.f, 0.f, 0.f);
            continue;
        }
        int beg = g_rowptr[d], end = g_rowptr[d + 1];
        float a0 = 0.f, a1 = 0.f, a2 = 0.f, a3 = 0.f;
        int idx = beg;
        if (tin32) {
            for (; idx + 6 <= end; idx += 6) {
                int4 c0 = g_csr[idx + 0];
                int4 c1 = g_csr[idx + 1];
                int4 c2 = g_csr[idx + 2];
                int4 c3 = g_csr[idx + 3];
                int4 c4 = g_csr[idx + 4];
                int4 c5 = g_csr[idx + 5];
                float4 t0 = *(const float4*)&tin32[c0.x * HH + jo];
                float4 t1 = *(const float4*)&tin32[c1.x * HH + jo];
                float4 t2 = *(const float4*)&tin32[c2.x * HH + jo];
                float4 t3 = *(const float4*)&tin32[c3.x * HH + jo];
                float4 t4 = *(const float4*)&tin32[c4.x * HH + jo];
                float4 t5 = *(const float4*)&tin32[c5.x * HH + jo];
                float n0 = __int_as_float(c0.z), n1 = __int_as_float(c1.z);
                float n2 = __int_as_float(c2.z), n3 = __int_as_float(c3.z);
                float n4 = __int_as_float(c4.z), n5 = __int_as_float(c5.z);
                a0 = fmaf(n0, t0.x, a0); a1 = fmaf(n0, t0.y, a1);
                a2 = fmaf(n0, t0.z, a2); a3 = fmaf(n0, t0.w, a3);
                a0 = fmaf(n1, t1.x, a0); a1 = fmaf(n1, t1.y, a1);
                a2 = fmaf(n1, t1.z, a2); a3 = fmaf(n1, t1.w, a3);
                a0 = fmaf(n2, t2.x, a0); a1 = fmaf(n2, t2.y, a1);
                a2 = fmaf(n2, t2.z, a2); a3 = fmaf(n2, t2.w, a3);
                a0 = fmaf(n3, t3.x, a0); a1 = fmaf(n3, t3.y, a1);
                a2 = fmaf(n3, t3.z, a2); a3 = fmaf(n3, t3.w, a3);
                a0 = fmaf(n4, t4.x, a0); a1 = fmaf(n4, t4.y, a1);
                a2 = fmaf(n4, t4.z, a2); a3 = fmaf(n4, t4.w, a3);
                a0 = fmaf(n5, t5.x, a0); a1 = fmaf(n5, t5.y, a1);
                a2 = fmaf(n5, t5.z, a2); a3 = fmaf(n5, t5.w, a3);
            }
            for (; idx < end; idx++) {
                int4 c = g_csr[idx];
                float nrm = __int_as_float(c.z);
                float4 t = *(const float4*)&tin32[c.x * HH + jo];
                a0 = fmaf(nrm, t.x, a0); a1 = fmaf(nrm, t.y, a1);
                a2 = fmaf(nrm, t.z, a2); a3 = fmaf(nrm, t.w, a3);
            }
        } else {
            int hb = lane * 2;   // half2 index within 64-wide row
            for (; idx + 6 <= end; idx += 6) {
                int4 c0 = g_csr[idx + 0];
                int4 c1 = g_csr[idx + 1];
                int4 c2 = g_csr[idx + 2];
                int4 c3 = g_csr[idx + 3];
                int4 c4 = g_csr[idx + 4];
                int4 c5 = g_csr[idx + 5];
                uint2 r0 = *(const uint2*)&tin16[c0.x * 64 + hb];
                uint2 r1 = *(const uint2*)&tin16[c1.x * 64 + hb];
                uint2 r2 = *(const uint2*)&tin16[c2.x * 64 + hb];
                uint2 r3 = *(const uint2*)&tin16[c3.x * 64 + hb];
                uint2 r4 = *(const uint2*)&tin16[c4.x * 64 + hb];
                uint2 r5 = *(const uint2*)&tin16[c5.x * 64 + hb];
                float n0 = __int_as_float(c0.z), n1 = __int_as_float(c1.z);
                float n2 = __int_as_float(c2.z), n3 = __int_as_float(c3.z);
                float n4 = __int_as_float(c4.z), n5 = __int_as_float(c5.z);
                float2 l0 = __half22float2(*(__half2*)&r0.x), h0v = __half22float2(*(__half2*)&r0.y);
                float2 l1 = __half22float2(*(__half2*)&r1.x), h1v = __half22float2(*(__half2*)&r1.y);
                float2 l2 = __half22float2(*(__half2*)&r2.x), h2v = __half22float2(*(__half2*)&r2.y);
                float2 l3 = __half22float2(*(__half2*)&r3.x), h3v = __half22float2(*(__half2*)&r3.y);
                float2 l4 = __half22float2(*(__half2*)&r4.x), h4v = __half22float2(*(__half2*)&r4.y);
                float2 l5 = __half22float2(*(__half2*)&r5.x), h5v = __half22float2(*(__half2*)&r5.y);
                a0 = fmaf(n0, l0.x, a0); a1 = fmaf(n0, l0.y, a1);
                a2 = fmaf(n0, h0v.x, a2); a3 = fmaf(n0, h0v.y, a3);
                a0 = fmaf(n1, l1.x, a0); a1 = fmaf(n1, l1.y, a1);
                a2 = fmaf(n1, h1v.x, a2); a3 = fmaf(n1, h1v.y, a3);
                a0 = fmaf(n2, l2.x, a0); a1 = fmaf(n2, l2.y, a1);
                a2 = fmaf(n2, h2v.x, a2); a3 = fmaf(n2, h2v.y, a3);
                a0 = fmaf(n3, l3.x, a0); a1 = fmaf(n3, l3.y, a1);
                a2 = fmaf(n3, h3v.x, a2); a3 = fmaf(n3, h3v.y, a3);
                a0 = fmaf(n4, l4.x, a0); a1 = fmaf(n4, l4.y, a1);
                a2 = fmaf(n4, h4v.x, a2); a3 = fmaf(n4, h4v.y, a3);
                a0 = fmaf(n5, l5.x, a0); a1 = fmaf(n5, l5.y, a1);
                a2 = fmaf(n5, h5v.x, a2); a3 = fmaf(n5, h5v.y, a3);
            }
            for (; idx < end; idx++) {
                int4 c = g_csr[idx];
                float nrm = __int_as_float(c.z);
                uint2 rr = *(const uint2*)&tin16[c.x * 64 + hb];
                float2 lo = __half22float2(*(__half2*)&rr.x);
                float2 hi = __half22float2(*(__half2*)&rr.y);
                a0 = fmaf(nrm, lo.x, a0); a1 = fmaf(nrm, lo.y, a1);
                a2 = fmaf(nrm, hi.x, a2); a3 = fmaf(nrm, hi.y, a3);
            }
        }
        float4 r = make_float4(a0, a1, a2, a3);
        *(float4*)&st[(w * 4 + i) * HH + jo] = r;
        if (tout16) {
            uint2 pk;
            *(__half2*)&pk.x = __floats2half2_rn(a0, a1);
            *(__half2*)&pk.y = __floats2half2_rn(a2, a3);
            *(uint2*)&tout16[d * 64 + lane * 2] = pk;
        }
    }
    __syncthreads();
    mm_tile(sw, st, Cin, Cout, HH, flags, bias, vbase, w, lane);
}

// ---------------- EA gather core (2-edge software pipeline) ----------------
__device__ __forceinline__ void ea_gather_node(int d, int jo, int lane,
                                               const float* __restrict__ eattr,
                                               const float* __restrict__ sw1,
                                               const float* __restrict__ sb1,
                                               float& a0, float& a1, float& a2, float& a3) {
    int beg = g_rowptr[d], end = g_rowptr[d + 1];
    float4 ad = *(const float4*)&g_adst[d * HH + jo];
    ull zb0 = pkxy(ad.x + sb1[jo], ad.y + sb1[jo + 1]);
    ull zb1 = pkxy(ad.z + sb1[jo + 2], ad.w + sb1[jo + 3]);
    a0 = a1 = a2 = a3 = 0.f;
    int idx = beg;
    for (; idx + 2 <= end; idx += 2) {
        int4 c0 = g_csr[idx];
        int4 c1 = g_csr[idx + 1];
        float ea0 = (lane < 16) ? eattr[c0.y * 16 + lane] : 0.f;
        float ea1 = (lane < 16) ? eattr[c1.y * 16 + lane] : 0.f;
        ulonglong2 as0 = *(const ulonglong2*)&g_asrc[c0.x * HH + jo];
        ulonglong2 as1 = *(const ulonglong2*)&g_asrc[c1.x * HH + jo];
        ull z00 = add2(zb0, as0.x), z01 = add2(zb1, as0.y);
        ull z10 = add2(zb0, as1.x), z11 = add2(zb1, as1.y);
#pragma unroll
        for (int q = 0; q < 16; q++) {
            float aq0 = __shfl_sync(0xffffffffu, ea0, q);
            float aq1 = __shfl_sync(0xffffffffu, ea1, q);
            ulonglong2 wv = *(const ulonglong2*)&sw1[q * HH + jo];
            ull p0 = pk2(aq0), p1 = pk2(aq1);
            z00 = fma2(p0, wv.x, z00); z01 = fma2(p0, wv.y, z01);
            z10 = fma2(p1, wv.x, z10); z11 = fma2(p1, wv.y, z11);
        }
        float f0, f1, f2, f3, g0, g1, g2, g3;
        upk(z00, f0, f1); upk(z01, f2, f3);
        upk(z10, g0, g1); upk(z11, g2, g3);
        a0 += fmaxf(f0, 0.f) + fmaxf(g0, 0.f);
        a1 += fmaxf(f1, 0.f) + fmaxf(g1, 0.f);
        a2 += fmaxf(f2, 0.f) + fmaxf(g2, 0.f);
        a3 += fmaxf(f3, 0.f) + fmaxf(g3, 0.f);
    }
    for (; idx < end; idx++) {
        int4 c = g_csr[idx];
        float eav = (lane < 16) ? eattr[c.y * 16 + lane] : 0.f;
        ulonglong2 as = *(const ulonglong2*)&g_asrc[c.x * HH + jo];
        ull z0 = add2(zb0, as.x);
        ull z1 = add2(zb1, as.y);
#pragma unroll
        for (int q = 0; q < 16; q++) {
            float a = __shfl_sync(0xffffffffu, eav, q);
            ull ap = pk2(a);
            ulonglong2 wv = *(const ulonglong2*)&sw1[q * HH + jo];
            z0 = fma2(ap, wv.x, z0);
            z1 = fma2(ap, wv.y, z1);
        }
        float f0, f1, f2, f3;
        upk(z0, f0, f1);
        upk(z1, f2, f3);
        a0 += fmaxf(f0, 0.f); a1 += fmaxf(f1, 0.f);
        a2 += fmaxf(f2, 0.f); a3 += fmaxf(f3, 0.f);
    }
}

// ---------------- fused EA gather + w2 projection ----------------
__global__ void __launch_bounds__(TB2, 2)
k_eagmm(const float* __restrict__ eattr,
        const float* __restrict__ w1ea, const float* __restrict__ b1,
        const float* __restrict__ w2, const float* __restrict__ b2,
        float* __restrict__ Cout) {
    extern __shared__ float sm[];
    float* sw2 = sm;               // 128*128
    float* st = sw2 + HH * HH;     // 64*128
    float* sw1 = st + TILE * HH;   // 16*128
    float* sb1 = sw1 + 16 * HH;    // 128
    int tid = threadIdx.x;
    load_w(w2, sw2, HH * HH, tid);
    for (int i = tid; i < 16 * HH; i += TB2) sw1[i] = w1ea[i];
    for (int i = tid; i < HH; i += TB2) sb1[i] = b1[i];
    int w = tid >> 5, lane = tid & 31;
    int jo = lane * 4;
    int vbase = blockIdx.x * TILE;
    __syncthreads();
#pragma unroll
    for (int i = 0; i < 4; i++) {
        int d = vbase + w * 4 + i;
        if (d >= NN) {
            *(float4*)&st[(w * 4 + i) * HH + jo] = make_float4(0.f, 0.f, 0.f, 0.f);
            continue;
        }
        float a0, a1, a2, a3;
        ea_gather_node(d, jo, lane, eattr, sw1, sb1, a0, a1, a2, a3);
        *(float4*)&st[(w * 4 + i) * HH + jo] = make_float4(a0, a1, a2, a3);
    }
    __syncthreads();
    mm_tile(sw2, st, nullptr, Cout, HH, MM_RELU | MM_BIASDEG, b2, vbase, w, lane);
}

// ---------------- EA2: gather + O=16 projection -> d_out ----------------
__global__ void k_ea_gather16(const float* __restrict__ eattr,
                              const float* __restrict__ w1ea, const float* __restrict__ b1,
                              const float* __restrict__ w2, const float* __restrict__ b2,
                              float* __restrict__ out) {
    extern __shared__ float sm[];
    float* sw1 = sm;             // 16*128
    float* sb1 = sm + 16 * HH;   // 128
    float* sw2t = sb1 + HH;      // 16*128 transposed
    float* sb2 = sw2t + HH * 16;
    float* buf = sb2 + 16;       // 8*128
    int tid = threadIdx.x;
    for (int i = tid; i < 16 * HH; i += blockDim.x) sw1[i] = w1ea[i];
    for (int i = tid; i < HH; i += blockDim.x) sb1[i] = b1[i];
    for (int i = tid; i < HH * 16; i += blockDim.x) {
        int j = i >> 4, o = i & 15;
        sw2t[o * HH + j] = w2[i];
    }
    if (tid < 16) sb2[tid] = b2[tid];
    __syncthreads();

    int w = tid >> 5, lane = tid & 31;
    int jo = lane * 4;
    for (int d = blockIdx.x * 8 + w; d < NN; d += gridDim.x * 8) {
        float a0, a1, a2, a3;
        ea_gather_node(d, jo, lane, eattr, sw1, sb1, a0, a1, a2, a3);
        *(float4*)&buf[w * HH + jo] = make_float4(a0, a1, a2, a3);
        __syncwarp();
        if (lane < 16) {
            int o = lane;
            float acc = g_degf[d] * sb2[o];
            for (int j4 = 0; j4 < HH; j4 += 4) {
                float4 b = *(const float4*)&buf[w * HH + j4];
                float4 wv = *(const float4*)&sw2t[o * HH + j4];
                acc = fmaf(b.x, wv.x, acc); acc = fmaf(b.y, wv.y, acc);
                acc = fmaf(b.z, wv.z, acc); acc = fmaf(b.w, wv.w, acc);
            }
            out[d * 16 + o] = acc;
        }
        __syncwarp();
    }
}

// ---------------- host ----------------
extern "C" void kernel_launch(void* const* d_in, const int* in_sizes, int n_in,
                              void* d_out, int out_size) {
    int eidx, wb;
    if (in_sizes[3] == 2 * EE) { eidx = 3; wb = 4; }
    else                       { eidx = n_in - 1; wb = 3; }

    const float* x     = (const float*)d_in[0];
    const float* mask  = (const float*)d_in[1];
    const float* eattr = (const float*)d_in[2];
    const int*   ei    = (const int*)d_in[eidx];
    const float* m_w1   = (const float*)d_in[wb + 0];
    const float* m_b1   = (const float*)d_in[wb + 1];
    const float* m_w2   = (const float*)d_in[wb + 2];
    const float* m_b2   = (const float*)d_in[wb + 3];
    const float* ea0_w1 = (const float*)d_in[wb + 4];
    const float* ea0_b1 = (const float*)d_in[wb + 5];
    const float* ea0_w2 = (const float*)d_in[wb + 6];
    const float* ea0_b2 = (const float*)d_in[wb + 7];
    const float* tag0_w = (const float*)d_in[wb + 8];
    const float* tag0_b = (const float*)d_in[wb + 9];
    const float* ea1_w1 = (const float*)d_in[wb + 10];
    const float* ea1_b1 = (const float*)d_in[wb + 11];
    const float* ea1_w2 = (const float*)d_in[wb + 12];
    const float* ea1_b2 = (const float*)d_in[wb + 13];
    const float* tag1_w = (const float*)d_in[wb + 14];
    const float* tag1_b = (const float*)d_in[wb + 15];
    const float* ea2_w1 = (const float*)d_in[wb + 16];
    const float* ea2_b1 = (const float*)d_in[wb + 17];
    const float* ea2_w2 = (const float*)d_in[wb + 18];
    const float* ea2_b2 = (const float*)d_in[wb + 19];

    float *p_h, *p_adst, *p_asrc, *p_out;
    __half2 *p_ta, *p_tb;
    cudaGetSymbolAddress((void**)&p_h, g_h);
    cudaGetSymbolAddress((void**)&p_adst, g_adst);
    cudaGetSymbolAddress((void**)&p_asrc, g_asrc);
    cudaGetSymbolAddress((void**)&p_out, g_out);
    cudaGetSymbolAddress((void**)&p_ta, g_t16a);
    cudaGetSymbolAddress((void**)&p_tb, g_t16b);

    static bool attr_done = false;
    if (!attr_done) {
        cudaFuncSetAttribute(k_mm, cudaFuncAttributeMaxDynamicSharedMemorySize, 100 * 1024);
        cudaFuncSetAttribute(k_mm2, cudaFuncAttributeMaxDynamicSharedMemorySize, 100 * 1024);
        cudaFuncSetAttribute(k_propmm, cudaFuncAttributeMaxDynamicSharedMemorySize, 100 * 1024);
        cudaFuncSetAttribute(k_eagmm, cudaFuncAttributeMaxDynamicSharedMemorySize, 108 * 1024);
        cudaFuncSetAttribute(k_ea_gather16, cudaFuncAttributeMaxDynamicSharedMemorySize, 48 * 1024);
        attr_done = true;
    }

    const int TB = 256;
    const int gN = (NN + TB - 1) / TB;   // 79
    const int gE = (E2 + TB - 1) / TB;
    const int gW = 2500;
    const size_t smm128 = (size_t)(HH * HH + TILE * HH) * 4;                 // 96KB
    const size_t smm16  = (size_t)(16 * HH + TILE * 16) * 4;                 // 12KB
    const size_t sgm    = (size_t)(HH * HH + TILE * HH + 16 * HH + HH) * 4;  // ~104.5KB
    const size_t sga16  = (size_t)(16 * HH + HH + HH * 16 + 16 + 8 * HH) * 4;

    // CSR + mask MLP
    k_zero_maskmlp<<<2 * gN, TB>>>(x, mask, m_w1, m_b1, m_w2, m_b2, p_h, gN);
    k_count<<<gE, TB>>>(ei);
    k_scanA<<<20, 1024>>>();
    k_scanB<<<20, 1024>>>();
    k_fill<<<gE, TB>>>(ei);

    // ---- EA0 (F=16) ----
    k_mm2<<<dim3(NT, 2), TB2, smm16>>>(p_h, ea0_w1, p_adst, p_asrc, 16);
    k_eagmm<<<NT, TB2, sgm>>>(eattr, ea0_w1 + 2 * 16 * HH, ea0_b1, ea0_w2, ea0_b2, p_h);

    // ---- TAG0 ----
    k_mm<<<NT, TB2, smm128>>>(p_h, tag0_w, nullptr, p_out, HH, 0, nullptr);
    k_propmm<<<NT, TB2, smm128>>>(p_h, nullptr, p_ta, tag0_w + 1 * HH * HH,
                                  p_out, p_out, MM_ACC, nullptr);
    k_propmm<<<NT, TB2, smm128>>>(nullptr, p_ta, p_tb, tag0_w + 2 * HH * HH,
                                  p_out, p_out, MM_ACC, nullptr);
    k_propmm<<<NT, TB2, smm128>>>(nullptr, p_tb, nullptr, tag0_w + 3 * HH * HH,
                                  p_out, p_h, MM_ACC | MM_RELU | MM_BIAS, tag0_b);

    // ---- EA1 (F=128) ----
    k_mm2<<<dim3(NT, 2), TB2, smm128>>>(p_h, ea1_w1, p_adst, p_asrc, HH);
    k_eagmm<<<NT, TB2, sgm>>>(eattr, ea1_w1 + 2 * HH * HH, ea1_b1, ea1_w2, ea1_b2, p_h);

    // ---- TAG1 ----
    k_mm<<<NT, TB2, smm128>>>(p_h, tag1_w, nullptr, p_out, HH, 0, nullptr);
    k_propmm<<<NT, TB2, smm128>>>(p_h, nullptr, p_ta, tag1_w + 1 * HH * HH,
                                  p_out, p_out, MM_ACC, nullptr);
    k_propmm<<<NT, TB2, smm128>>>(nullptr, p_ta, p_tb, tag1_w + 2 * HH * HH,
                                  p_out, p_out, MM_ACC, nullptr);
    k_propmm<<<NT, TB2, smm128>>>(nullptr, p_tb, nullptr, tag1_w + 3 * HH * HH,
                                  p_out, p_h, MM_ACC | MM_RELU | MM_BIAS, tag1_b);

    // ---- EA2 (F=128, OUT=16, no relu) -> d_out ----
    k_mm2<<<dim3(NT, 2), TB2, smm128>>>(p_h, ea2_w1, p_adst, p_asrc, HH);
    k_ea_gather16<<<gW, TB, sga16>>>(eattr, ea2_w1 + 2 * HH * HH, ea2_b1,
                                     ea2_w2, ea2_b2, (float*)d_out);
}

// round 15
// speedup vs baseline: 1.2061x; 1.0175x over previous
#include <cuda_runtime.h>
#include <cuda_fp16.h>

#define NN 20000
#define EE 160000
#define E2 320000
#define HH 128
#define TILE 64
#define NT ((NN + TILE - 1) / TILE)   // 313
#define TB2 512

#define MM_ACC 1
#define MM_RELU 2
#define MM_BIAS 4
#define MM_BIASDEG 8
#define MM_HALF 16

typedef unsigned long long ull;

__device__ __forceinline__ ull pk2(float x) {
    ull r; asm("mov.b64 %0,{%1,%1};" : "=l"(r) : "f"(x)); return r;
}
__device__ __forceinline__ ull pkxy(float x, float y) {
    ull r; asm("mov.b64 %0,{%1,%2};" : "=l"(r) : "f"(x), "f"(y)); return r;
}
__device__ __forceinline__ ull fma2(ull a, ull b, ull c) {
    ull d; asm("fma.rn.f32x2 %0,%1,%2,%3;" : "=l"(d) : "l"(a), "l"(b), "l"(c)); return d;
}
__device__ __forceinline__ ull add2(ull a, ull b) {
    ull d; asm("add.rn.f32x2 %0,%1,%2;" : "=l"(d) : "l"(a), "l"(b)); return d;
}
__device__ __forceinline__ void upk(ull v, float& x, float& y) {
    asm("mov.b64 {%0,%1},%2;" : "=f"(x), "=f"(y) : "l"(v));
}

// ---------------- scratch ----------------
__device__ float g_h[NN * HH];
__device__ float g_adst[NN * HH];
__device__ __half2 g_asrc16[NN * 64];   // fp16 source-side projection
__device__ float g_out[NN * HH];
__device__ __half2 g_t16a[NN * 64];     // fp16 TAG intermediates
__device__ __half2 g_t16b[NN * 64];
__device__ float g_dis[NN];
__device__ float g_degf[NN];
__device__ int g_rowptr[NN + 1];
__device__ int g_cursor[NN];
__device__ int g_blocksum[32];
__device__ int4 g_csr[E2];   // (src, ea_row, bitcast(norm), 0)

// ---------------- fused: zero cursor + mask MLP ----------------
__global__ void k_zero_maskmlp(const float* __restrict__ x, const float* __restrict__ mask,
                               const float* __restrict__ w1, const float* __restrict__ b1,
                               const float* __restrict__ w2, const float* __restrict__ b2,
                               float* __restrict__ hout, int zblocks) {
    if ((int)blockIdx.x < zblocks) {
        int i = blockIdx.x * blockDim.x + threadIdx.x;
        if (i < NN) g_cursor[i] = 0;
        return;
    }
    __shared__ float sw1[16 * HH], sb1[HH], sw2[HH * 16], sb2[16];
    for (int i = threadIdx.x; i < 16 * HH; i += blockDim.x) { sw1[i] = w1[i]; sw2[i] = w2[i]; }
    for (int i = threadIdx.x; i < HH; i += blockDim.x) sb1[i] = b1[i];
    if (threadIdx.x < 16) sb2[threadIdx.x] = b2[threadIdx.x];
    __syncthreads();
    int v = (blockIdx.x - zblocks) * blockDim.x + threadIdx.x;
    if (v >= NN) return;
    float m[16], out[16];
#pragma unroll
    for (int i = 0; i < 16; i++) m[i] = mask[v * 16 + i];
#pragma unroll
    for (int o = 0; o < 16; o++) out[o] = sb2[o];
#pragma unroll 4
    for (int j = 0; j < HH; j++) {
        float a = sb1[j];
#pragma unroll
        for (int i = 0; i < 16; i++) a = fmaf(m[i], sw1[i * HH + j], a);
        a = fmaxf(a, 0.f);
#pragma unroll
        for (int o = 0; o < 16; o++) out[o] = fmaf(a, sw2[j * 16 + o], out[o]);
    }
#pragma unroll
    for (int o = 0; o < 16; o++) hout[v * 16 + o] = out[o] + x[v * 16 + o];
}

__global__ void k_count(const int* __restrict__ ei) {
    int e = blockIdx.x * blockDim.x + threadIdx.x;
    if (e >= E2) return;
    int d = (e < EE) ? ei[e + EE] : ei[e - EE];
    atomicAdd(&g_cursor[d], 1);
}

// 20 blocks x 1000; per-block exclusive scan; zero cursor; compute deg/dis
__global__ void k_scanA() {
    __shared__ int s[1024];
    int tid = threadIdx.x;
    int i = blockIdx.x * 1000 + tid;
    bool ok = (tid < 1000 && i < NN);
    int v = ok ? g_cursor[i] : 0;
    if (ok) {
        g_cursor[i] = 0;
        float df = (float)v;
        g_degf[i] = df;
        g_dis[i] = v > 0 ? rsqrtf(df) : 0.f;
    }
    s[tid] = v;
    __syncthreads();
    for (int off = 1; off < 1024; off <<= 1) {
        int t = (tid >= off) ? s[tid - off] : 0;
        __syncthreads();
        s[tid] += t;
        __syncthreads();
    }
    if (ok) g_rowptr[i] = s[tid] - v;
    if (tid == 1023) g_blocksum[blockIdx.x] = s[1023];
}

__global__ void k_scanB() {
    int b = blockIdx.x;
    int off = 0, tot = 0;
#pragma unroll
    for (int k = 0; k < 20; k++) {
        int bs = g_blocksum[k];
        if (k < b) off += bs;
        tot += bs;
    }
    int i = b * 1000 + threadIdx.x;
    if (threadIdx.x < 1000 && i < NN) g_rowptr[i] += off;
    if (b == 19 && threadIdx.x == 0) g_rowptr[NN] = tot;
}

__global__ void k_fill(const int* __restrict__ ei) {
    int e = blockIdx.x * blockDim.x + threadIdx.x;
    if (e >= E2) return;
    int srow, d, er;
    if (e < EE) { srow = ei[e]; d = ei[e + EE]; er = e; }
    else        { srow = ei[e]; d = ei[e - EE]; er = e - EE; }
    int idx = g_rowptr[d] + atomicAdd(&g_cursor[d], 1);
    float nrm = g_dis[srow] * g_dis[d];
    g_csr[idx] = make_int4(srow, er, __float_as_int(nrm), 0);
}

// ---------------- tile-MM core: 64-node tile, 16 warps, 4 nodes/warp ----------------
__device__ __forceinline__ void mm_tile(const float* __restrict__ sw, const float* __restrict__ sh,
                                        const float* __restrict__ Cin, float* __restrict__ Cout,
                                        int F, int flags, const float* __restrict__ bias,
                                        int vbase, int w, int lane) {
    ull acc[4][2];
#pragma unroll
    for (int i = 0; i < 4; i++) { acc[i][0] = 0ull; acc[i][1] = 0ull; }
    const float* h0 = &sh[(w * 4 + 0) * F];
    const float* h1 = &sh[(w * 4 + 1) * F];
    const float* h2 = &sh[(w * 4 + 2) * F];
    const float* h3 = &sh[(w * 4 + 3) * F];
    for (int j4 = 0; j4 < F; j4 += 4) {
        float4 hv0 = *(const float4*)&h0[j4];
        float4 hv1 = *(const float4*)&h1[j4];
        float4 hv2 = *(const float4*)&h2[j4];
        float4 hv3 = *(const float4*)&h3[j4];
#pragma unroll
        for (int jj = 0; jj < 4; jj++) {
            ulonglong2 wv = *(const ulonglong2*)&sw[(j4 + jj) * HH + lane * 4];
            float f0 = jj == 0 ? hv0.x : jj == 1 ? hv0.y : jj == 2 ? hv0.z : hv0.w;
            float f1 = jj == 0 ? hv1.x : jj == 1 ? hv1.y : jj == 2 ? hv1.z : hv1.w;
            float f2 = jj == 0 ? hv2.x : jj == 1 ? hv2.y : jj == 2 ? hv2.z : hv2.w;
            float f3 = jj == 0 ? hv3.x : jj == 1 ? hv3.y : jj == 2 ? hv3.z : hv3.w;
            ull a0 = pk2(f0), a1 = pk2(f1), a2 = pk2(f2), a3 = pk2(f3);
            acc[0][0] = fma2(a0, wv.x, acc[0][0]); acc[0][1] = fma2(a0, wv.y, acc[0][1]);
            acc[1][0] = fma2(a1, wv.x, acc[1][0]); acc[1][1] = fma2(a1, wv.y, acc[1][1]);
            acc[2][0] = fma2(a2, wv.x, acc[2][0]); acc[2][1] = fma2(a2, wv.y, acc[2][1]);
            acc[3][0] = fma2(a3, wv.x, acc[3][0]); acc[3][1] = fma2(a3, wv.y, acc[3][1]);
        }
    }
    int o = lane * 4;
#pragma unroll
    for (int i = 0; i < 4; i++) {
        int v = vbase + w * 4 + i;
        if (v >= NN) continue;
        float4 r;
        upk(acc[i][0], r.x, r.y);
        upk(acc[i][1], r.z, r.w);
        if (flags & MM_BIAS) {
            r.x += bias[o]; r.y += bias[o + 1]; r.z += bias[o + 2]; r.w += bias[o + 3];
        }
        if (flags & MM_BIASDEG) {
            float dg = g_degf[v];
            r.x += dg * bias[o]; r.y += dg * bias[o + 1];
            r.z += dg * bias[o + 2]; r.w += dg * bias[o + 3];
        }
        if (flags & MM_ACC) {
            float4 c = *(const float4*)&Cin[v * HH + o];
            r.x += c.x; r.y += c.y; r.z += c.z; r.w += c.w;
        }
        if (flags & MM_RELU) {
            r.x = fmaxf(r.x, 0.f); r.y = fmaxf(r.y, 0.f);
            r.z = fmaxf(r.z, 0.f); r.w = fmaxf(r.w, 0.f);
        }
        if (flags & MM_HALF) {
            uint2 pk;
            *(__half2*)&pk.x = __floats2half2_rn(r.x, r.y);
            *(__half2*)&pk.y = __floats2half2_rn(r.z, r.w);
            *(uint2*)&((__half2*)Cout)[v * 64 + lane * 2] = pk;
        } else {
            *(float4*)&Cout[v * HH + o] = r;
        }
    }
}

__device__ __forceinline__ void load_w(const float* __restrict__ W, float* __restrict__ sw,
                                       int n, int tid) {
    for (int i = tid * 4; i < n; i += TB2 * 4)
        *(float4*)&sw[i] = *(const float4*)&W[i];
}

__device__ __forceinline__ void load_tile(const float* __restrict__ A, float* __restrict__ sh,
                                          int vbase, int F, int tid) {
    for (int i = tid * 4; i < TILE * F; i += TB2 * 4) {
        int g = vbase * F + i;
        float4 v = (g < NN * F) ? *(const float4*)&A[g] : make_float4(0.f, 0.f, 0.f, 0.f);
        *(float4*)&sh[i] = v;
    }
}

// ---------------- plain tiled matmul ----------------
__global__ void __launch_bounds__(TB2, 2)
k_mm(const float* __restrict__ A, const float* __restrict__ W,
     const float* __restrict__ Cin, float* __restrict__ Cout,
     int F, int flags, const float* __restrict__ bias) {
    extern __shared__ float sm[];
    float* sw = sm;
    float* sh = sm + F * HH;
    int tid = threadIdx.x;
    load_w(W, sw, F * HH, tid);
    int vbase = blockIdx.x * TILE;
    load_tile(A, sh, vbase, F, tid);
    __syncthreads();
    mm_tile(sw, sh, Cin, Cout, F, flags, bias, vbase, tid >> 5, tid & 31);
}

// ---------------- dual matmul: y=0 -> fp32 adst, y=1 -> fp16 asrc ----------------
__global__ void __launch_bounds__(TB2, 2)
k_mm2(const float* __restrict__ A, const float* __restrict__ Wbase,
      float* __restrict__ C0, __half2* __restrict__ C1, int F) {
    extern __shared__ float sm[];
    float* sw = sm;
    float* sh = sm + F * HH;
    int tid = threadIdx.x;
    const float* W = Wbase + blockIdx.y * F * HH;
    load_w(W, sw, F * HH, tid);
    int vbase = blockIdx.x * TILE;
    load_tile(A, sh, vbase, F, tid);
    __syncthreads();
    if (blockIdx.y)
        mm_tile(sw, sh, nullptr, (float*)C1, F, MM_HALF, nullptr, vbase, tid >> 5, tid & 31);
    else
        mm_tile(sw, sh, nullptr, C0, F, 0, nullptr, vbase, tid >> 5, tid & 31);
}

// ---------------- fused prop + matmul (6-edge pipeline; fp32 or fp16 input) ----------------
__global__ void __launch_bounds__(TB2, 2)
k_propmm(const float* __restrict__ tin32, const __half2* __restrict__ tin16,
         __half2* __restrict__ tout16,
         const float* __restrict__ W,
         const float* __restrict__ Cin, float* __restrict__ Cout,
         int flags, const float* __restrict__ bias) {
    extern __shared__ float sm[];
    float* sw = sm;              // 128*128
    float* st = sm + HH * HH;    // 64*128
    int tid = threadIdx.x;
    load_w(W, sw, HH * HH, tid);
    int w = tid >> 5, lane = tid & 31;
    int jo = lane * 4;
    int vbase = blockIdx.x * TILE;
#pragma unroll
    for (int i = 0; i < 4; i++) {
        int d = vbase + w * 4 + i;
        if (d >= NN) {
            *(float4*)&st[(w * 4 + i) * HH + jo] = make_float4(0.f, 0.f, 0.f, 0.f);
            continue;
        }
        int beg = g_rowptr[d], end = g_rowptr[d + 1];
        float a0 = 0.f, a1 = 0.f, a2 = 0.f, a3 = 0.f;
        int idx = beg;
        if (tin32) {
            for (; idx + 6 <= end; idx += 6) {
                int4 c0 = g_csr[idx + 0];
                int4 c1 = g_csr[idx + 1];
                int4 c2 = g_csr[idx + 2];
                int4 c3 = g_csr[idx + 3];
                int4 c4 = g_csr[idx + 4];
                int4 c5 = g_csr[idx + 5];
                float4 t0 = *(const float4*)&tin32[c0.x * HH + jo];
                float4 t1 = *(const float4*)&tin32[c1.x * HH + jo];
                float4 t2 = *(const float4*)&tin32[c2.x * HH + jo];
                float4 t3 = *(const float4*)&tin32[c3.x * HH + jo];
                float4 t4 = *(const float4*)&tin32[c4.x * HH + jo];
                float4 t5 = *(const float4*)&tin32[c5.x * HH + jo];
                float n0 = __int_as_float(c0.z), n1 = __int_as_float(c1.z);
                float n2 = __int_as_float(c2.z), n3 = __int_as_float(c3.z);
                float n4 = __int_as_float(c4.z), n5 = __int_as_float(c5.z);
                a0 = fmaf(n0, t0.x, a0); a1 = fmaf(n0, t0.y, a1);
                a2 = fmaf(n0, t0.z, a2); a3 = fmaf(n0, t0.w, a3);
                a0 = fmaf(n1, t1.x, a0); a1 = fmaf(n1, t1.y, a1);
                a2 = fmaf(n1, t1.z, a2); a3 = fmaf(n1, t1.w, a3);
                a0 = fmaf(n2, t2.x, a0); a1 = fmaf(n2, t2.y, a1);
                a2 = fmaf(n2, t2.z, a2); a3 = fmaf(n2, t2.w, a3);
                a0 = fmaf(n3, t3.x, a0); a1 = fmaf(n3, t3.y, a1);
                a2 = fmaf(n3, t3.z, a2); a3 = fmaf(n3, t3.w, a3);
                a0 = fmaf(n4, t4.x, a0); a1 = fmaf(n4, t4.y, a1);
                a2 = fmaf(n4, t4.z, a2); a3 = fmaf(n4, t4.w, a3);
                a0 = fmaf(n5, t5.x, a0); a1 = fmaf(n5, t5.y, a1);
                a2 = fmaf(n5, t5.z, a2); a3 = fmaf(n5, t5.w, a3);
            }
            for (; idx < end; idx++) {
                int4 c = g_csr[idx];
                float nrm = __int_as_float(c.z);
                float4 t = *(const float4*)&tin32[c.x * HH + jo];
                a0 = fmaf(nrm, t.x, a0); a1 = fmaf(nrm, t.y, a1);
                a2 = fmaf(nrm, t.z, a2); a3 = fmaf(nrm, t.w, a3);
            }
        } else {
            int hb = lane * 2;
            for (; idx + 6 <= end; idx += 6) {
                int4 c0 = g_csr[idx + 0];
                int4 c1 = g_csr[idx + 1];
                int4 c2 = g_csr[idx + 2];
                int4 c3 = g_csr[idx + 3];
                int4 c4 = g_csr[idx + 4];
                int4 c5 = g_csr[idx + 5];
                uint2 r0 = *(const uint2*)&tin16[c0.x * 64 + hb];
                uint2 r1 = *(const uint2*)&tin16[c1.x * 64 + hb];
                uint2 r2 = *(const uint2*)&tin16[c2.x * 64 + hb];
                uint2 r3 = *(const uint2*)&tin16[c3.x * 64 + hb];
                uint2 r4 = *(const uint2*)&tin16[c4.x * 64 + hb];
                uint2 r5 = *(const uint2*)&tin16[c5.x * 64 + hb];
                float n0 = __int_as_float(c0.z), n1 = __int_as_float(c1.z);
                float n2 = __int_as_float(c2.z), n3 = __int_as_float(c3.z);
                float n4 = __int_as_float(c4.z), n5 = __int_as_float(c5.z);
                float2 l0 = __half22float2(*(__half2*)&r0.x), h0v = __half22float2(*(__half2*)&r0.y);
                float2 l1 = __half22float2(*(__half2*)&r1.x), h1v = __half22float2(*(__half2*)&r1.y);
                float2 l2 = __half22float2(*(__half2*)&r2.x), h2v = __half22float2(*(__half2*)&r2.y);
                float2 l3 = __half22float2(*(__half2*)&r3.x), h3v = __half22float2(*(__half2*)&r3.y);
                float2 l4 = __half22float2(*(__half2*)&r4.x), h4v = __half22float2(*(__half2*)&r4.y);
                float2 l5 = __half22float2(*(__half2*)&r5.x), h5v = __half22float2(*(__half2*)&r5.y);
                a0 = fmaf(n0, l0.x, a0); a1 = fmaf(n0, l0.y, a1);
                a2 = fmaf(n0, h0v.x, a2); a3 = fmaf(n0, h0v.y, a3);
                a0 = fmaf(n1, l1.x, a0); a1 = fmaf(n1, l1.y, a1);
                a2 = fmaf(n1, h1v.x, a2); a3 = fmaf(n1, h1v.y, a3);
                a0 = fmaf(n2, l2.x, a0); a1 = fmaf(n2, l2.y, a1);
                a2 = fmaf(n2, h2v.x, a2); a3 = fmaf(n2, h2v.y, a3);
                a0 = fmaf(n3, l3.x, a0); a1 = fmaf(n3, l3.y, a1);
                a2 = fmaf(n3, h3v.x, a2); a3 = fmaf(n3, h3v.y, a3);
                a0 = fmaf(n4, l4.x, a0); a1 = fmaf(n4, l4.y, a1);
                a2 = fmaf(n4, h4v.x, a2); a3 = fmaf(n4, h4v.y, a3);
                a0 = fmaf(n5, l5.x, a0); a1 = fmaf(n5, l5.y, a1);
                a2 = fmaf(n5, h5v.x, a2); a3 = fmaf(n5, h5v.y, a3);
            }
            for (; idx < end; idx++) {
                int4 c = g_csr[idx];
                float nrm = __int_as_float(c.z);
                uint2 rr = *(const uint2*)&tin16[c.x * 64 + hb];
                float2 lo = __half22float2(*(__half2*)&rr.x);
                float2 hi = __half22float2(*(__half2*)&rr.y);
                a0 = fmaf(nrm, lo.x, a0); a1 = fmaf(nrm, lo.y, a1);
                a2 = fmaf(nrm, hi.x, a2); a3 = fmaf(nrm, hi.y, a3);
            }
        }
        float4 r = make_float4(a0, a1, a2, a3);
        *(float4*)&st[(w * 4 + i) * HH + jo] = r;
        if (tout16) {
            uint2 pk;
            *(__half2*)&pk.x = __floats2half2_rn(a0, a1);
            *(__half2*)&pk.y = __floats2half2_rn(a2, a3);
            *(uint2*)&tout16[d * 64 + lane * 2] = pk;
        }
    }
    __syncthreads();
    mm_tile(sw, st, Cin, Cout, HH, flags, bias, vbase, w, lane);
}

// ---------------- EA gather core (2-edge pipeline, fp16 asrc) ----------------
__device__ __forceinline__ void ea_gather_node(int d, int jo, int lane,
                                               const float* __restrict__ eattr,
                                               const float* __restrict__ sw1,
                                               const float* __restrict__ sb1,
                                               float& a0, float& a1, float& a2, float& a3) {
    int beg = g_rowptr[d], end = g_rowptr[d + 1];
    int hb = lane * 2;
    float4 ad = *(const float4*)&g_adst[d * HH + jo];
    ull zb0 = pkxy(ad.x + sb1[jo], ad.y + sb1[jo + 1]);
    ull zb1 = pkxy(ad.z + sb1[jo + 2], ad.w + sb1[jo + 3]);
    a0 = a1 = a2 = a3 = 0.f;
    int idx = beg;
    for (; idx + 2 <= end; idx += 2) {
        int4 c0 = g_csr[idx];
        int4 c1 = g_csr[idx + 1];
        float ea0 = (lane < 16) ? eattr[c0.y * 16 + lane] : 0.f;
        float ea1 = (lane < 16) ? eattr[c1.y * 16 + lane] : 0.f;
        uint2 as0 = *(const uint2*)&g_asrc16[c0.x * 64 + hb];
        uint2 as1 = *(const uint2*)&g_asrc16[c1.x * 64 + hb];
        float2 s0l = __half22float2(*(__half2*)&as0.x), s0h = __half22float2(*(__half2*)&as0.y);
        float2 s1l = __half22float2(*(__half2*)&as1.x), s1h = __half22float2(*(__half2*)&as1.y);
        ull z00 = add2(zb0, pkxy(s0l.x, s0l.y)), z01 = add2(zb1, pkxy(s0h.x, s0h.y));
        ull z10 = add2(zb0, pkxy(s1l.x, s1l.y)), z11 = add2(zb1, pkxy(s1h.x, s1h.y));
#pragma unroll
        for (int q = 0; q < 16; q++) {
            float aq0 = __shfl_sync(0xffffffffu, ea0, q);
            float aq1 = __shfl_sync(0xffffffffu, ea1, q);
            ulonglong2 wv = *(const ulonglong2*)&sw1[q * HH + jo];
            ull p0 = pk2(aq0), p1 = pk2(aq1);
            z00 = fma2(p0, wv.x, z00); z01 = fma2(p0, wv.y, z01);
            z10 = fma2(p1, wv.x, z10); z11 = fma2(p1, wv.y, z11);
        }
        float f0, f1, f2, f3, g0, g1, g2, g3;
        upk(z00, f0, f1); upk(z01, f2, f3);
        upk(z10, g0, g1); upk(z11, g2, g3);
        a0 += fmaxf(f0, 0.f) + fmaxf(g0, 0.f);
        a1 += fmaxf(f1, 0.f) + fmaxf(g1, 0.f);
        a2 += fmaxf(f2, 0.f) + fmaxf(g2, 0.f);
        a3 += fmaxf(f3, 0.f) + fmaxf(g3, 0.f);
    }
    for (; idx < end; idx++) {
        int4 c = g_csr[idx];
        float eav = (lane < 16) ? eattr[c.y * 16 + lane] : 0.f;
        uint2 as = *(const uint2*)&g_asrc16[c.x * 64 + hb];
        float2 sl = __half22float2(*(__half2*)&as.x), sh2 = __half22float2(*(__half2*)&as.y);
        ull z0 = add2(zb0, pkxy(sl.x, sl.y));
        ull z1 = add2(zb1, pkxy(sh2.x, sh2.y));
#pragma unroll
        for (int q = 0; q < 16; q++) {
            float a = __shfl_sync(0xffffffffu, eav, q);
            ull ap = pk2(a);
            ulonglong2 wv = *(const ulonglong2*)&sw1[q * HH + jo];
            z0 = fma2(ap, wv.x, z0);
            z1 = fma2(ap, wv.y, z1);
        }
        float f0, f1, f2, f3;
        upk(z0, f0, f1);
        upk(z1, f2, f3);
        a0 += fmaxf(f0, 0.f); a1 += fmaxf(f1, 0.f);
        a2 += fmaxf(f2, 0.f); a3 += fmaxf(f3, 0.f);
    }
}

// ---------------- fused EA gather + w2 projection ----------------
__global__ void __launch_bounds__(TB2, 2)
k_eagmm(const float* __restrict__ eattr,
        const float* __restrict__ w1ea, const float* __restrict__ b1,
        const float* __restrict__ w2, const float* __restrict__ b2,
        float* __restrict__ Cout) {
    extern __shared__ float sm[];
    float* sw2 = sm;               // 128*128
    float* st = sw2 + HH * HH;     // 64*128
    float* sw1 = st + TILE * HH;   // 16*128
    float* sb1 = sw1 + 16 * HH;    // 128
    int tid = threadIdx.x;
    load_w(w2, sw2, HH * HH, tid);
    for (int i = tid; i < 16 * HH; i += TB2) sw1[i] = w1ea[i];
    for (int i = tid; i < HH; i += TB2) sb1[i] = b1[i];
    int w = tid >> 5, lane = tid & 31;
    int jo = lane * 4;
    int vbase = blockIdx.x * TILE;
    __syncthreads();
#pragma unroll
    for (int i = 0; i < 4; i++) {
        int d = vbase + w * 4 + i;
        if (d >= NN) {
            *(float4*)&st[(w * 4 + i) * HH + jo] = make_float4(0.f, 0.f, 0.f, 0.f);
            continue;
        }
        float a0, a1, a2, a3;
        ea_gather_node(d, jo, lane, eattr, sw1, sb1, a0, a1, a2, a3);
        *(float4*)&st[(w * 4 + i) * HH + jo] = make_float4(a0, a1, a2, a3);
    }
    __syncthreads();
    mm_tile(sw2, st, nullptr, Cout, HH, MM_RELU | MM_BIASDEG, b2, vbase, w, lane);
}

// ---------------- EA2: gather + O=16 projection -> d_out ----------------
__global__ void k_ea_gather16(const float* __restrict__ eattr,
                              const float* __restrict__ w1ea, const float* __restrict__ b1,
                              const float* __restrict__ w2, const float* __restrict__ b2,
                              float* __restrict__ out) {
    extern __shared__ float sm[];
    float* sw1 = sm;             // 16*128
    float* sb1 = sm + 16 * HH;   // 128
    float* sw2t = sb1 + HH;      // 16*128 transposed
    float* sb2 = sw2t + HH * 16;
    float* buf = sb2 + 16;       // 8*128
    int tid = threadIdx.x;
    for (int i = tid; i < 16 * HH; i += blockDim.x) sw1[i] = w1ea[i];
    for (int i = tid; i < HH; i += blockDim.x) sb1[i] = b1[i];
    for (int i = tid; i < HH * 16; i += blockDim.x) {
        int j = i >> 4, o = i & 15;
        sw2t[o * HH + j] = w2[i];
    }
    if (tid < 16) sb2[tid] = b2[tid];
    __syncthreads();

    int w = tid >> 5, lane = tid & 31;
    int jo = lane * 4;
    for (int d = blockIdx.x * 8 + w; d < NN; d += gridDim.x * 8) {
        float a0, a1, a2, a3;
        ea_gather_node(d, jo, lane, eattr, sw1, sb1, a0, a1, a2, a3);
        *(float4*)&buf[w * HH + jo] = make_float4(a0, a1, a2, a3);
        __syncwarp();
        if (lane < 16) {
            int o = lane;
            float acc = g_degf[d] * sb2[o];
            for (int j4 = 0; j4 < HH; j4 += 4) {
                float4 b = *(const float4*)&buf[w * HH + j4];
                float4 wv = *(const float4*)&sw2t[o * HH + j4];
                acc = fmaf(b.x, wv.x, acc); acc = fmaf(b.y, wv.y, acc);
                acc = fmaf(b.z, wv.z, acc); acc = fmaf(b.w, wv.w, acc);
            }
            out[d * 16 + o] = acc;
        }
        __syncwarp();
    }
}

// ---------------- host ----------------
extern "C" void kernel_launch(void* const* d_in, const int* in_sizes, int n_in,
                              void* d_out, int out_size) {
    int eidx, wb;
    if (in_sizes[3] == 2 * EE) { eidx = 3; wb = 4; }
    else                       { eidx = n_in - 1; wb = 3; }

    const float* x     = (const float*)d_in[0];
    const float* mask  = (const float*)d_in[1];
    const float* eattr = (const float*)d_in[2];
    const int*   ei    = (const int*)d_in[eidx];
    const float* m_w1   = (const float*)d_in[wb + 0];
    const float* m_b1   = (const float*)d_in[wb + 1];
    const float* m_w2   = (const float*)d_in[wb + 2];
    const float* m_b2   = (const float*)d_in[wb + 3];
    const float* ea0_w1 = (const float*)d_in[wb + 4];
    const float* ea0_b1 = (const float*)d_in[wb + 5];
    const float* ea0_w2 = (const float*)d_in[wb + 6];
    const float* ea0_b2 = (const float*)d_in[wb + 7];
    const float* tag0_w = (const float*)d_in[wb + 8];
    const float* tag0_b = (const float*)d_in[wb + 9];
    const float* ea1_w1 = (const float*)d_in[wb + 10];
    const float* ea1_b1 = (const float*)d_in[wb + 11];
    const float* ea1_w2 = (const float*)d_in[wb + 12];
    const float* ea1_b2 = (const float*)d_in[wb + 13];
    const float* tag1_w = (const float*)d_in[wb + 14];
    const float* tag1_b = (const float*)d_in[wb + 15];
    const float* ea2_w1 = (const float*)d_in[wb + 16];
    const float* ea2_b1 = (const float*)d_in[wb + 17];
    const float* ea2_w2 = (const float*)d_in[wb + 18];
    const float* ea2_b2 = (const float*)d_in[wb + 19];

    float *p_h, *p_adst, *p_out;
    __half2 *p_asrc16, *p_ta, *p_tb;
    cudaGetSymbolAddress((void**)&p_h, g_h);
    cudaGetSymbolAddress((void**)&p_adst, g_adst);
    cudaGetSymbolAddress((void**)&p_asrc16, g_asrc16);
    cudaGetSymbolAddress((void**)&p_out, g_out);
    cudaGetSymbolAddress((void**)&p_ta, g_t16a);
    cudaGetSymbolAddress((void**)&p_tb, g_t16b);

    static bool attr_done = false;
    if (!attr_done) {
        cudaFuncSetAttribute(k_mm, cudaFuncAttributeMaxDynamicSharedMemorySize, 100 * 1024);
        cudaFuncSetAttribute(k_mm2, cudaFuncAttributeMaxDynamicSharedMemorySize, 100 * 1024);
        cudaFuncSetAttribute(k_propmm, cudaFuncAttributeMaxDynamicSharedMemorySize, 100 * 1024);
        cudaFuncSetAttribute(k_eagmm, cudaFuncAttributeMaxDynamicSharedMemorySize, 108 * 1024);
        cudaFuncSetAttribute(k_ea_gather16, cudaFuncAttributeMaxDynamicSharedMemorySize, 48 * 1024);
        attr_done = true;
    }

    const int TB = 256;
    const int gN = (NN + TB - 1) / TB;   // 79
    const int gE = (E2 + TB - 1) / TB;
    const int gW = 2500;
    const size_t smm128 = (size_t)(HH * HH + TILE * HH) * 4;                 // 96KB
    const size_t smm16  = (size_t)(16 * HH + TILE * 16) * 4;                 // 12KB
    const size_t sgm    = (size_t)(HH * HH + TILE * HH + 16 * HH + HH) * 4;  // ~104.5KB
    const size_t sga16  = (size_t)(16 * HH + HH + HH * 16 + 16 + 8 * HH) * 4;

    // CSR + mask MLP
    k_zero_maskmlp<<<2 * gN, TB>>>(x, mask, m_w1, m_b1, m_w2, m_b2, p_h, gN);
    k_count<<<gE, TB>>>(ei);
    k_scanA<<<20, 1024>>>();
    k_scanB<<<20, 1024>>>();
    k_fill<<<gE, TB>>>(ei);

    // ---- EA0 (F=16) ----
    k_mm2<<<dim3(NT, 2), TB2, smm16>>>(p_h, ea0_w1, p_adst, p_asrc16, 16);
    k_eagmm<<<NT, TB2, sgm>>>(eattr, ea0_w1 + 2 * 16 * HH, ea0_b1, ea0_w2, ea0_b2, p_h);

    // ---- TAG0 ----
    k_mm<<<NT, TB2, smm128>>>(p_h, tag0_w, nullptr, p_out, HH, 0, nullptr);
    k_propmm<<<NT, TB2, smm128>>>(p_h, nullptr, p_ta, tag0_w + 1 * HH * HH,
                                  p_out, p_out, MM_ACC, nullptr);
    k_propmm<<<NT, TB2, smm128>>>(nullptr, p_ta, p_tb, tag0_w + 2 * HH * HH,
                                  p_out, p_out, MM_ACC, nullptr);
    k_propmm<<<NT, TB2, smm128>>>(nullptr, p_tb, nullptr, tag0_w + 3 * HH * HH,
                                  p_out, p_h, MM_ACC | MM_RELU | MM_BIAS, tag0_b);

    // ---- EA1 (F=128) ----
    k_mm2<<<dim3(NT, 2), TB2, smm128>>>(p_h, ea1_w1, p_adst, p_asrc16, HH);
    k_eagmm<<<NT, TB2, sgm>>>(eattr, ea1_w1 + 2 * HH * HH, ea1_b1, ea1_w2, ea1_b2, p_h);

    // ---- TAG1 ----
    k_mm<<<NT, TB2, smm128>>>(p_h, tag1_w, nullptr, p_out, HH, 0, nullptr);
    k_propmm<<<NT, TB2, smm128>>>(p_h, nullptr, p_ta, tag1_w + 1 * HH * HH,
                                  p_out, p_out, MM_ACC, nullptr);
    k_propmm<<<NT, TB2, smm128>>>(nullptr, p_ta, p_tb, tag1_w + 2 * HH * HH,
                                  p_out, p_out, MM_ACC, nullptr);
    k_propmm<<<NT, TB2, smm128>>>(nullptr, p_tb, nullptr, tag1_w + 3 * HH * HH,
                                  p_out, p_h, MM_ACC | MM_RELU | MM_BIAS, tag1_b);

    // ---- EA2 (F=128, OUT=16, no relu) -> d_out ----
    k_mm2<<<dim3(NT, 2), TB2, smm128>>>(p_h, ea2_w1, p_adst, p_asrc16, HH);
    k_ea_gather16<<<gW, TB, sga16>>>(eattr, ea2_w1 + 2 * HH * HH, ea2_b1,
                                     ea2_w2, ea2_b2, (float*)d_out);
}